// round 10
// baseline (speedup 1.0000x reference)
#include <cuda_runtime.h>
#include <cuda_bf16.h>
#include <cstdint>

// ---------------------------------------------------------------------------
// LocalWindowTransformer on sm_103 (mma.sync HMMA path).
//   GEMM1: qkv = x @ Win^T + b_in   [16384 x 3072], K=1024
//   attn : per (window, head) online-softmax(qk^T/8)v  (fp32 FFMA2)
//   GEMM3: out = att @ Wout^T + b_out [16384 x 1024], K=1024
// fp32 GEMM via bf16 3-split: Ah*Bh + Ah*Bl + Al*Bh, fp32 accum HMMA.
// R10: BK=64, 256 threads, register fragment double-buffering so ldmatrix of
//      ks+1 overlaps the MMAs of ks (kills the LDSM/MMA phase lockstep).
// ---------------------------------------------------------------------------

#define M_TOK   16384
#define HDIM    1024
#define QKVDIM  3072
#define NHEAD   16
#define HD      64
#define WIN     128
#define NWIN    128

// ---- device scratch (no cudaMalloc allowed) --------------------------------
__device__ float  g_qkv [(size_t)M_TOK * QKVDIM];          // 192 MiB fp32
__device__ uint4  g_xh  [(size_t)M_TOK * HDIM / 8];        // 32 MiB bf16
__device__ uint4  g_xl  [(size_t)M_TOK * HDIM / 8];
__device__ uint4  g_wih [(size_t)QKVDIM * HDIM / 8];       // 6 MiB
__device__ uint4  g_wil [(size_t)QKVDIM * HDIM / 8];
__device__ uint4  g_woh [(size_t)HDIM * HDIM / 8];         // 2 MiB
__device__ uint4  g_wol [(size_t)HDIM * HDIM / 8];
__device__ uint4  g_ah  [(size_t)M_TOK * HDIM / 8];        // 32 MiB (attn out)
__device__ uint4  g_al  [(size_t)M_TOK * HDIM / 8];

// ---- helpers ---------------------------------------------------------------
__device__ __forceinline__ uint32_t smem_u32(const void* p) {
    uint32_t a;
    asm("{ .reg .u64 t; cvta.to.shared.u64 t, %1; cvt.u32.u64 %0, t; }"
        : "=r"(a) : "l"(p));
    return a;
}
__device__ __forceinline__ void cp16(uint32_t dst, const void* src) {
    asm volatile("cp.async.cg.shared.global [%0], [%1], 16;"
                 :: "r"(dst), "l"(src));
}

#define LDSM4(r, a) \
    asm volatile("ldmatrix.sync.aligned.m8n8.x4.shared.b16 {%0,%1,%2,%3}, [%4];" \
                 : "=r"((r)[0]), "=r"((r)[1]), "=r"((r)[2]), "=r"((r)[3]) \
                 : "r"(a))

#define MMA(c, a, b0, b1) \
    asm volatile("mma.sync.aligned.m16n8k16.row.col.f32.bf16.bf16.f32 " \
                 "{%0,%1,%2,%3}, {%4,%5,%6,%7}, {%8,%9}, {%0,%1,%2,%3};" \
                 : "+f"((c)[0]), "+f"((c)[1]), "+f"((c)[2]), "+f"((c)[3]) \
                 : "r"((a)[0]), "r"((a)[1]), "r"((a)[2]), "r"((a)[3]), \
                   "r"(b0), "r"(b1))

union U8 { uint4 q; __nv_bfloat16 b[8]; };

// ---------------------------------------------------------------------------
// split fp32 row-major -> bf16 hi/lo row-major. 1 thread = 8 values.
// ---------------------------------------------------------------------------
__global__ __launch_bounds__(256)
void split_rm(const float4* __restrict__ src,
              uint4* __restrict__ hi, uint4* __restrict__ lo)
{
    int u = blockIdx.x * 256 + threadIdx.x;
    float4 a = src[2 * u], b = src[2 * u + 1];
    float v[8] = {a.x, a.y, a.z, a.w, b.x, b.y, b.z, b.w};
    U8 H, L;
#pragma unroll
    for (int j = 0; j < 8; ++j) {
        __nv_bfloat16 hb = __float2bfloat16(v[j]);
        H.b[j] = hb;
        L.b[j] = __float2bfloat16(v[j] - __bfloat162float(hb));
    }
    hi[u] = H.q;
    lo[u] = L.q;
}

// ---------------------------------------------------------------------------
// HMMA NT GEMM: C[M,N] = A[M,1024] * B[N,1024]^T + bias (fp32 via bf16 split)
// BM=128, BN=128, BK=64, 256 threads (8 warps, 2x4), warp tile 64x32.
// smem rows = 64 bf16 = 128B padded to 144B (conflict-free ldmatrix phases).
// 3-stage cp.async, one barrier per K-tile (16 tiles), register fragment
// double-buffer: LDSM of ks+1 issued before MMAs of ks.
// ---------------------------------------------------------------------------
#define ARRB   18432            /* 128 rows x 144B */
#define OFF_AL 18432
#define OFF_BH 36864
#define OFF_BL 55296
#define STAGE  73728            /* Ah|Al|Bh|Bl */
#define KT     16               /* 1024 / 64 */
#define GEMM_SMEM (3 * STAGE)   /* 221184 B */

__global__ __launch_bounds__(256, 1)
void gemm_mma(const __nv_bfloat16* __restrict__ Ah,
              const __nv_bfloat16* __restrict__ Al,
              const __nv_bfloat16* __restrict__ Bh,
              const __nv_bfloat16* __restrict__ Bl,
              const float* __restrict__ bias,
              float* __restrict__ C, int N)
{
    extern __shared__ char smem_raw[];
    const uint32_t sb = smem_u32(smem_raw);

    const int tid  = threadIdx.x;
    const int lane = tid & 31;
    const int wid  = tid >> 5;
    const int wm   = wid & 1;           // 0..1  (64-row halves)
    const int wn   = wid >> 1;          // 0..3  (32-col quarters)
    const int bm   = blockIdx.x;
    const int bn   = blockIdx.y;

    // --- per-thread load slots: each array 128 rows x 8 units(16B);
    //     thread -> row = tid>>1, 4 consecutive units ((tid&1)*4 ..+3)
    const int lrow = tid >> 1;
    const int lcu  = (tid & 1) * 4;
    const uint32_t dL = lrow * 144 + lcu * 16;

    const __nv_bfloat16* pAh = Ah + (size_t)(bm * 128 + lrow) * 1024 + lcu * 8;
    const __nv_bfloat16* pAl = Al + (size_t)(bm * 128 + lrow) * 1024 + lcu * 8;
    const __nv_bfloat16* pBh = Bh + (size_t)(bn * 128 + lrow) * 1024 + lcu * 8;
    const __nv_bfloat16* pBl = Bl + (size_t)(bn * 128 + lrow) * 1024 + lcu * 8;

    // --- per-thread ldmatrix bases ---
    const uint32_t a_off = (uint32_t)((wm * 64 + (lane & 15)) * 144 + (lane >> 4) * 16);
    const uint32_t b_off = (uint32_t)(OFF_BH + (wn * 32 + (lane & 15)) * 144 + (lane >> 4) * 16);

    float acc[4][4][4];
#pragma unroll
    for (int i = 0; i < 4; ++i)
#pragma unroll
        for (int j = 0; j < 4; ++j)
#pragma unroll
            for (int k = 0; k < 4; ++k) acc[i][j][k] = 0.f;

    // --- issue one stage's loads into smem slot ---
    auto issue = [&](uint32_t st, int ko) {
#pragma unroll
        for (int i = 0; i < 4; ++i) {
            cp16(st + dL + i * 16,          pAh + ko + i * 8);
            cp16(st + OFF_AL + dL + i * 16, pAl + ko + i * 8);
            cp16(st + OFF_BH + dL + i * 16, pBh + ko + i * 8);
            cp16(st + OFF_BL + dL + i * 16, pBl + ko + i * 8);
        }
    };

    // prologue: stages 0 and 1
    issue(sb, 0);
    asm volatile("cp.async.commit_group;" ::: "memory");
    issue(sb + STAGE, 64);
    asm volatile("cp.async.commit_group;" ::: "memory");

    int cs = 0;       // compute slot
    int ws = 2;       // write slot (stage t+2)
    for (int t = 0; t < KT; ++t) {
        asm volatile("cp.async.wait_group 1;" ::: "memory");
        __syncthreads();   // stage t visible; all warps done with slot t-1

        if (t + 2 < KT)
            issue(sb + ws * STAGE, (t + 2) * 64);
        asm volatile("cp.async.commit_group;" ::: "memory");
        ws = (ws == 2) ? 0 : ws + 1;

        const uint32_t st = sb + cs * STAGE;
        cs = (cs == 2) ? 0 : cs + 1;
        const uint32_t ab = st + a_off;
        const uint32_t bb = st + b_off;

        // register fragment double buffers
        uint32_t fah[2][4][4], fal[2][4][4], fbh[2][2][4], fbl[2][2][4];

#define LOADF(B, KB)                                                          \
        do {                                                                  \
            _Pragma("unroll")                                                 \
            for (int mt = 0; mt < 4; ++mt) {                                  \
                LDSM4(fah[B][mt], ab + mt * 2304 + (KB));                     \
                LDSM4(fal[B][mt], ab + OFF_AL + mt * 2304 + (KB));            \
            }                                                                 \
            _Pragma("unroll")                                                 \
            for (int np = 0; np < 2; ++np) {                                  \
                LDSM4(fbh[B][np], bb + np * 2304 + (KB));                     \
                LDSM4(fbl[B][np], bb + (OFF_BL - OFF_BH) + np * 2304 + (KB)); \
            }                                                                 \
        } while (0)

        LOADF(0, 0);
#pragma unroll
        for (int ks = 0; ks < 4; ++ks) {
            const int cb = ks & 1;
            if (ks < 3) {
                if (cb) LOADF(0, (ks + 1) * 32);
                else    LOADF(1, (ks + 1) * 32);
            }
            // pass 1: Ah*Bh  (16 independent MMAs)
#pragma unroll
            for (int mt = 0; mt < 4; ++mt)
#pragma unroll
                for (int nt = 0; nt < 4; ++nt) {
                    const int np = nt >> 1, s = nt & 1;
                    MMA(acc[mt][nt], fah[cb][mt], fbh[cb][np][s], fbh[cb][np][s + 2]);
                }
            // pass 2: Ah*Bl
#pragma unroll
            for (int mt = 0; mt < 4; ++mt)
#pragma unroll
                for (int nt = 0; nt < 4; ++nt) {
                    const int np = nt >> 1, s = nt & 1;
                    MMA(acc[mt][nt], fah[cb][mt], fbl[cb][np][s], fbl[cb][np][s + 2]);
                }
            // pass 3: Al*Bh
#pragma unroll
            for (int mt = 0; mt < 4; ++mt)
#pragma unroll
                for (int nt = 0; nt < 4; ++nt) {
                    const int np = nt >> 1, s = nt & 1;
                    MMA(acc[mt][nt], fal[cb][mt], fbh[cb][np][s], fbh[cb][np][s + 2]);
                }
        }
#undef LOADF
    }

    // --- epilogue: register frags -> GMEM with bias ---
#pragma unroll
    for (int mt = 0; mt < 4; ++mt) {
#pragma unroll
        for (int nt = 0; nt < 4; ++nt) {
            const float* c = acc[mt][nt];
            const int row = bm * 128 + wm * 64 + mt * 16 + (lane >> 2);
            const int col = bn * 128 + wn * 32 + nt * 8 + (lane & 3) * 2;
            const float b0 = __ldg(bias + col);
            const float b1 = __ldg(bias + col + 1);
            *(float2*)(C + (size_t)row * N + col) =
                make_float2(c[0] + b0, c[1] + b1);
            *(float2*)(C + (size_t)(row + 8) * N + col) =
                make_float2(c[2] + b0, c[3] + b1);
        }
    }
}

// ---------------------------------------------------------------------------
// Windowed attention: online (chunked flash) softmax, fp32 packed-f32x2 math.
// One CTA per (window, head), 128 threads, thread = query row. smem = K+V only.
// ---------------------------------------------------------------------------
__device__ __forceinline__ unsigned long long pk2(float lo, float hi) {
    unsigned long long r;
    asm("mov.b64 %0, {%1, %2};" : "=l"(r) : "f"(lo), "f"(hi));
    return r;
}
__device__ __forceinline__ void upk2(float& lo, float& hi, unsigned long long v) {
    asm("mov.b64 {%0, %1}, %2;" : "=f"(lo), "=f"(hi) : "l"(v));
}
__device__ __forceinline__ void ffma2(unsigned long long& c,
                                      unsigned long long a,
                                      unsigned long long b) {
    asm("fma.rn.f32x2 %0, %1, %2, %0;" : "+l"(c) : "l"(a), "l"(b));
}
__device__ __forceinline__ void fmul2(unsigned long long& c,
                                      unsigned long long a) {
    asm("mul.rn.f32x2 %0, %0, %1;" : "+l"(c) : "l"(a));
}

#define ATTN_SMEM ((8192 + 8192) * 4)

__global__ __launch_bounds__(128)
void attn_kernel(const float* __restrict__ qkv,
                 uint4* __restrict__ oh, uint4* __restrict__ ol)
{
    extern __shared__ float sm[];
    float* Ks = sm;               // [128][64]
    float* Vs = sm + 8192;        // [128][64]

    const int w    = blockIdx.x;
    const int hd_i = blockIdx.y;
    const int tid  = threadIdx.x;

    const size_t base = (size_t)w * WIN * QKVDIM;
    const float* Kg = qkv + base + HDIM     + hd_i * HD;
    const float* Vg = qkv + base + 2 * HDIM + hd_i * HD;

    for (int idx = tid; idx < WIN * HD; idx += 128) {
        int row = idx >> 6, d = idx & 63;
        Ks[idx] = Kg[(size_t)row * QKVDIM + d];
        Vs[idx] = Vg[(size_t)row * QKVDIM + d];
    }

    const float4* Qg = (const float4*)(qkv + base + (size_t)tid * QKVDIM + hd_i * HD);
    unsigned long long q2[32];
#pragma unroll
    for (int i = 0; i < 16; ++i) {
        float4 v = Qg[i];
        q2[2*i]   = pk2(v.x, v.y);
        q2[2*i+1] = pk2(v.z, v.w);
    }
    __syncthreads();

    const unsigned long long* K2 = (const unsigned long long*)Ks;
    const unsigned long long* V2 = (const unsigned long long*)Vs;

    float m = -1e30f, l = 0.f;
    unsigned long long o2[32];
#pragma unroll
    for (int d = 0; d < 32; ++d) o2[d] = 0ull;

    for (int c = 0; c < 8; ++c) {             // 8 chunks of 16 keys
        float s[16];
#pragma unroll
        for (int jj = 0; jj < 16; ++jj) {
            const int j = c * 16 + jj;
            unsigned long long a0 = 0, a1 = 0, a2 = 0, a3 = 0;
            const unsigned long long* kj = K2 + j * 32;
#pragma unroll
            for (int d = 0; d < 32; d += 4) {
                ffma2(a0, q2[d+0], kj[d+0]);
                ffma2(a1, q2[d+1], kj[d+1]);
                ffma2(a2, q2[d+2], kj[d+2]);
                ffma2(a3, q2[d+3], kj[d+3]);
            }
            float lo, hi, ss;
            upk2(lo, hi, a0); ss  = lo + hi;
            upk2(lo, hi, a1); ss += lo + hi;
            upk2(lo, hi, a2); ss += lo + hi;
            upk2(lo, hi, a3); ss += lo + hi;
            s[jj] = ss * 0.125f;
        }
        float cm = s[0];
#pragma unroll
        for (int jj = 1; jj < 16; ++jj) cm = fmaxf(cm, s[jj]);
        const float nm = fmaxf(m, cm);
        const float sc = __expf(m - nm);
        m = nm;
        l *= sc;
        const unsigned long long sc2 = pk2(sc, sc);
#pragma unroll
        for (int d = 0; d < 32; ++d) fmul2(o2[d], sc2);
#pragma unroll
        for (int jj = 0; jj < 16; ++jj) {
            const float p = __expf(s[jj] - nm);
            l += p;
            const unsigned long long p2 = pk2(p, p);
            const unsigned long long* vj = V2 + (c * 16 + jj) * 32;
#pragma unroll
            for (int d = 0; d < 32; ++d) ffma2(o2[d], p2, vj[d]);
        }
    }

    const float inv = 1.0f / l;
    float ov[64];
#pragma unroll
    for (int d = 0; d < 32; ++d) {
        float lo, hi; upk2(lo, hi, o2[d]);
        ov[2*d]   = lo * inv;
        ov[2*d+1] = hi * inv;
    }

    // bf16 hi/lo split, row-major [M_TOK, 1024]
    const size_t obase = ((size_t)(w * WIN + tid) * HDIM + hd_i * HD) >> 3;
#pragma unroll
    for (int c8 = 0; c8 < 8; ++c8) {
        U8 H, L;
#pragma unroll
        for (int j = 0; j < 8; ++j) {
            float v = ov[c8 * 8 + j];
            __nv_bfloat16 hb = __float2bfloat16(v);
            H.b[j] = hb;
            L.b[j] = __float2bfloat16(v - __bfloat162float(hb));
        }
        oh[obase + c8] = H.q;
        ol[obase + c8] = L.q;
    }
}

// ---------------------------------------------------------------------------
extern "C" void kernel_launch(void* const* d_in, const int* in_sizes, int n_in,
                              void* d_out, int out_size)
{
    (void)in_sizes; (void)n_in; (void)out_size;
    const float* x     = (const float*)d_in[0];
    const float* w_in  = (const float*)d_in[1];
    const float* b_in  = (const float*)d_in[2];
    const float* w_out = (const float*)d_in[3];
    const float* b_out = (const float*)d_in[4];
    float* out = (float*)d_out;

    float* qkv;
    uint4 *xh, *xl, *wih, *wil, *woh, *wol, *ah, *al;
    cudaGetSymbolAddress((void**)&qkv, g_qkv);
    cudaGetSymbolAddress((void**)&xh,  g_xh);
    cudaGetSymbolAddress((void**)&xl,  g_xl);
    cudaGetSymbolAddress((void**)&wih, g_wih);
    cudaGetSymbolAddress((void**)&wil, g_wil);
    cudaGetSymbolAddress((void**)&woh, g_woh);
    cudaGetSymbolAddress((void**)&wol, g_wol);
    cudaGetSymbolAddress((void**)&ah,  g_ah);
    cudaGetSymbolAddress((void**)&al,  g_al);

    cudaFuncSetAttribute(gemm_mma,
                         cudaFuncAttributeMaxDynamicSharedMemorySize, GEMM_SMEM);
    cudaFuncSetAttribute(attn_kernel,
                         cudaFuncAttributeMaxDynamicSharedMemorySize, ATTN_SMEM);

    // split fp32 inputs into bf16 hi/lo (row-major)
    split_rm<<<(M_TOK  * HDIM) / 2048, 256>>>((const float4*)x,     xh,  xl);
    split_rm<<<(QKVDIM * HDIM) / 2048, 256>>>((const float4*)w_in,  wih, wil);
    split_rm<<<(HDIM   * HDIM) / 2048, 256>>>((const float4*)w_out, woh, wol);

    // Stage 1: QKV projection
    gemm_mma<<<dim3(M_TOK / 128, QKVDIM / 128), 256, GEMM_SMEM>>>(
        (const __nv_bfloat16*)xh, (const __nv_bfloat16*)xl,
        (const __nv_bfloat16*)wih, (const __nv_bfloat16*)wil,
        b_in, qkv, QKVDIM);

    // Stage 2: windowed attention (online softmax, emits bf16 hi/lo)
    attn_kernel<<<dim3(NWIN, NHEAD), 128, ATTN_SMEM>>>(qkv, ah, al);

    // Stage 3: output projection
    gemm_mma<<<dim3(M_TOK / 128, HDIM / 128), 256, GEMM_SMEM>>>(
        (const __nv_bfloat16*)ah, (const __nv_bfloat16*)al,
        (const __nv_bfloat16*)woh, (const __nv_bfloat16*)wol,
        b_out, out, HDIM);
}

// round 11
// speedup vs baseline: 1.6022x; 1.6022x over previous
#include <cuda_runtime.h>
#include <cuda_bf16.h>
#include <cstdint>

// ---------------------------------------------------------------------------
// LocalWindowTransformer on sm_103 (mma.sync tf32 path).
//   GEMM1: qkv = x @ Win^T + b_in   [16384 x 3072], K=1024
//   attn : per (window, head) online-softmax(qk^T/8)v  (fp32 FFMA2)
//   GEMM3: out = att @ Wout^T + b_out [16384 x 1024], K=1024
// GEMMs run single-product tf32 (mma.sync.m16n8k8.tf32, fp32 accum); inputs
// pre-rounded to tf32 with cvt.rna. Mainloop = R3's best-measured structure:
// BM=BN=128, BK=32, 256 thr, 2-stage cp.async, 2 CTAs/SM, XOR-swizzled smem.
// ---------------------------------------------------------------------------

#define M_TOK   16384
#define HDIM    1024
#define QKVDIM  3072
#define NHEAD   16
#define HD      64
#define WIN     128
#define NWIN    128

// ---- device scratch (no cudaMalloc allowed) --------------------------------
__device__ float g_qkv [(size_t)M_TOK * QKVDIM];    // 192 MiB
__device__ float g_xr  [(size_t)M_TOK * HDIM];      // 64 MiB (tf32-rounded x)
__device__ float g_wir [(size_t)QKVDIM * HDIM];     // 12 MiB
__device__ float g_wor [(size_t)HDIM * HDIM];       // 4 MiB
__device__ float g_att [(size_t)M_TOK * HDIM];      // 64 MiB (rounded attn out)

// ---- helpers ---------------------------------------------------------------
__device__ __forceinline__ uint32_t smem_u32(const void* p) {
    uint32_t a;
    asm("{ .reg .u64 t; cvta.to.shared.u64 t, %1; cvt.u32.u64 %0, t; }"
        : "=r"(a) : "l"(p));
    return a;
}
__device__ __forceinline__ void cp16(uint32_t dst, const void* src) {
    asm volatile("cp.async.cg.shared.global [%0], [%1], 16;"
                 :: "r"(dst), "l"(src));
}
__device__ __forceinline__ float rna_tf32(float v) {
    uint32_t r;
    asm("cvt.rna.tf32.f32 %0, %1;" : "=r"(r) : "f"(v));
    return __uint_as_float(r);
}

#define LDSM4(r, a) \
    asm volatile("ldmatrix.sync.aligned.m8n8.x4.shared.b16 {%0,%1,%2,%3}, [%4];" \
                 : "=r"((r)[0]), "=r"((r)[1]), "=r"((r)[2]), "=r"((r)[3]) \
                 : "r"(a))

#define MMAT(c, a, b0, b1) \
    asm volatile("mma.sync.aligned.m16n8k8.row.col.f32.tf32.tf32.f32 " \
                 "{%0,%1,%2,%3}, {%4,%5,%6,%7}, {%8,%9}, {%0,%1,%2,%3};" \
                 : "+f"((c)[0]), "+f"((c)[1]), "+f"((c)[2]), "+f"((c)[3]) \
                 : "r"((a)[0]), "r"((a)[1]), "r"((a)[2]), "r"((a)[3]), \
                   "r"(b0), "r"(b1))

// ---------------------------------------------------------------------------
// round fp32 -> tf32 (rna) elementwise. 1 thread = 4 values.
// ---------------------------------------------------------------------------
__global__ __launch_bounds__(256)
void round_tf32(const float4* __restrict__ src, float4* __restrict__ dst)
{
    int u = blockIdx.x * 256 + threadIdx.x;
    float4 v = src[u];
    v.x = rna_tf32(v.x); v.y = rna_tf32(v.y);
    v.z = rna_tf32(v.z); v.w = rna_tf32(v.w);
    dst[u] = v;
}

// ---------------------------------------------------------------------------
// tf32 NT GEMM: C[M,N] = A[M,1024] * B[N,1024]^T + bias
// BM=BN=128, BK=32 (fp32), 256 threads (8 warps 2x4), warp tile 64x32.
// smem tile: 128 rows x 128B, XOR swizzle (16B unit ^= row&7).
// 2-stage cp.async, two barriers per K-tile (R3 structure). 2 CTAs/SM.
// ldmatrix.b16 on the fp32 data (b16-pair view) yields tf32 fragments.
// ---------------------------------------------------------------------------
#define OFF_B  16384
#define STAGE  32768
#define KT     32               /* 1024 / 32 */
#define GEMM_SMEM (2 * STAGE)   /* 65536 B */

__global__ __launch_bounds__(256, 2)
void gemm_tf32(const float* __restrict__ A, const float* __restrict__ B,
               const float* __restrict__ bias, float* __restrict__ C, int N)
{
    extern __shared__ char smem_raw[];
    const uint32_t sb = smem_u32(smem_raw);

    const int tid  = threadIdx.x;
    const int lane = tid & 31;
    const int wid  = tid >> 5;
    const int wm   = wid & 1;           // 0..1  (64-row halves)
    const int wn   = wid >> 1;          // 0..3  (32-col quarters)
    const int bm   = blockIdx.x;
    const int bn   = blockIdx.y;

    // --- loader: thread -> row = tid>>1, 4 units of 16B ((tid&1)*4 ..+3) ---
    const int lrow = tid >> 1;
    const int lhu  = (tid & 1) * 4;
    const int lrm  = lrow & 7;
    uint32_t dstu[4];
#pragma unroll
    for (int i = 0; i < 4; ++i)
        dstu[i] = lrow * 128 + (((lhu + i) ^ lrm) << 4);

    const float* pA = A + (size_t)(bm * 128 + lrow) * 1024 + lhu * 4;
    const float* pB = B + (size_t)(bn * 128 + lrow) * 1024 + lhu * 4;

    auto issue = [&](uint32_t st, int ko) {
#pragma unroll
        for (int i = 0; i < 4; ++i) {
            cp16(st + dstu[i],         pA + ko + i * 4);
            cp16(st + OFF_B + dstu[i], pB + ko + i * 4);
        }
    };

    // --- ldmatrix row precompute ---
    // A tiles (per mt): row = wm*64 + mt*16 + ((lane>>3)&1)*8 + (lane&7)
    int rowA[4], rmA[4];
#pragma unroll
    for (int mt = 0; mt < 4; ++mt) {
        rowA[mt] = wm * 64 + mt * 16 + ((lane >> 3) & 1) * 8 + (lane & 7);
        rmA[mt]  = rowA[mt] & 7;
    }
    const int uaA = lane >> 4;              // k-half selector for A tiles
    // B tiles (per pair p): row = wn*32 + p*16 + (lane>>4)*8 + (lane&7)
    int rowB[2], rmB[2];
#pragma unroll
    for (int p = 0; p < 2; ++p) {
        rowB[p] = wn * 32 + p * 16 + (lane >> 4) * 8 + (lane & 7);
        rmB[p]  = rowB[p] & 7;
    }
    const int uaB = (lane >> 3) & 1;        // k-half selector for B tiles

    float acc[4][4][4];
#pragma unroll
    for (int i = 0; i < 4; ++i)
#pragma unroll
        for (int j = 0; j < 4; ++j)
#pragma unroll
            for (int k = 0; k < 4; ++k) acc[i][j][k] = 0.f;

    issue(sb, 0);
    asm volatile("cp.async.commit_group;" ::: "memory");

    for (int t = 0; t < KT; ++t) {
        if (t + 1 < KT) {
            issue(sb + ((t + 1) & 1) * STAGE, (t + 1) * 32);
            asm volatile("cp.async.commit_group;" ::: "memory");
            asm volatile("cp.async.wait_group 1;" ::: "memory");
        } else {
            asm volatile("cp.async.wait_group 0;" ::: "memory");
        }
        __syncthreads();                    // stage t visible

        const uint32_t st = sb + (t & 1) * STAGE;
#pragma unroll
        for (int ks = 0; ks < 4; ++ks) {
            uint32_t af[4][4], bf[2][4];
#pragma unroll
            for (int mt = 0; mt < 4; ++mt) {
                const uint32_t ad = st + rowA[mt] * 128 +
                                    (((ks * 2 + uaA) ^ rmA[mt]) << 4);
                LDSM4(af[mt], ad);
            }
#pragma unroll
            for (int p = 0; p < 2; ++p) {
                const uint32_t bd = st + OFF_B + rowB[p] * 128 +
                                    (((ks * 2 + uaB) ^ rmB[p]) << 4);
                LDSM4(bf[p], bd);
            }
#pragma unroll
            for (int mt = 0; mt < 4; ++mt) {
#pragma unroll
                for (int nt = 0; nt < 4; ++nt) {
                    const int p = nt >> 1, s = (nt & 1) * 2;
                    MMAT(acc[mt][nt], af[mt], bf[p][s], bf[p][s + 1]);
                }
            }
        }
        __syncthreads();                    // done reading stage t slot
    }

    // --- epilogue: register frags -> GMEM with bias ---
#pragma unroll
    for (int mt = 0; mt < 4; ++mt) {
#pragma unroll
        for (int nt = 0; nt < 4; ++nt) {
            const float* c = acc[mt][nt];
            const int row = bm * 128 + wm * 64 + mt * 16 + (lane >> 2);
            const int col = bn * 128 + wn * 32 + nt * 8 + (lane & 3) * 2;
            const float b0 = __ldg(bias + col);
            const float b1 = __ldg(bias + col + 1);
            *(float2*)(C + (size_t)row * N + col) =
                make_float2(c[0] + b0, c[1] + b1);
            *(float2*)(C + (size_t)(row + 8) * N + col) =
                make_float2(c[2] + b0, c[3] + b1);
        }
    }
}

// ---------------------------------------------------------------------------
// Windowed attention: online (chunked flash) softmax, fp32 packed-f32x2 math.
// One CTA per (window, head), 128 threads, thread = query row. smem = K+V.
// Output written as tf32-rounded fp32 (ready for GEMM3).
// ---------------------------------------------------------------------------
__device__ __forceinline__ unsigned long long pk2(float lo, float hi) {
    unsigned long long r;
    asm("mov.b64 %0, {%1, %2};" : "=l"(r) : "f"(lo), "f"(hi));
    return r;
}
__device__ __forceinline__ void upk2(float& lo, float& hi, unsigned long long v) {
    asm("mov.b64 {%0, %1}, %2;" : "=f"(lo), "=f"(hi) : "l"(v));
}
__device__ __forceinline__ void ffma2(unsigned long long& c,
                                      unsigned long long a,
                                      unsigned long long b) {
    asm("fma.rn.f32x2 %0, %1, %2, %0;" : "+l"(c) : "l"(a), "l"(b));
}
__device__ __forceinline__ void fmul2(unsigned long long& c,
                                      unsigned long long a) {
    asm("mul.rn.f32x2 %0, %0, %1;" : "+l"(c) : "l"(a));
}

#define ATTN_SMEM ((8192 + 8192) * 4)

__global__ __launch_bounds__(128)
void attn_kernel(const float* __restrict__ qkv, float* __restrict__ att)
{
    extern __shared__ float sm[];
    float* Ks = sm;               // [128][64]
    float* Vs = sm + 8192;        // [128][64]

    const int w    = blockIdx.x;
    const int hd_i = blockIdx.y;
    const int tid  = threadIdx.x;

    const size_t base = (size_t)w * WIN * QKVDIM;
    const float* Kg = qkv + base + HDIM     + hd_i * HD;
    const float* Vg = qkv + base + 2 * HDIM + hd_i * HD;

    for (int idx = tid; idx < WIN * HD; idx += 128) {
        int row = idx >> 6, d = idx & 63;
        Ks[idx] = Kg[(size_t)row * QKVDIM + d];
        Vs[idx] = Vg[(size_t)row * QKVDIM + d];
    }

    const float4* Qg = (const float4*)(qkv + base + (size_t)tid * QKVDIM + hd_i * HD);
    unsigned long long q2[32];
#pragma unroll
    for (int i = 0; i < 16; ++i) {
        float4 v = Qg[i];
        q2[2*i]   = pk2(v.x, v.y);
        q2[2*i+1] = pk2(v.z, v.w);
    }
    __syncthreads();

    const unsigned long long* K2 = (const unsigned long long*)Ks;
    const unsigned long long* V2 = (const unsigned long long*)Vs;

    float m = -1e30f, l = 0.f;
    unsigned long long o2[32];
#pragma unroll
    for (int d = 0; d < 32; ++d) o2[d] = 0ull;

    for (int c = 0; c < 8; ++c) {             // 8 chunks of 16 keys
        float s[16];
#pragma unroll
        for (int jj = 0; jj < 16; ++jj) {
            const int j = c * 16 + jj;
            unsigned long long a0 = 0, a1 = 0, a2 = 0, a3 = 0;
            const unsigned long long* kj = K2 + j * 32;
#pragma unroll
            for (int d = 0; d < 32; d += 4) {
                ffma2(a0, q2[d+0], kj[d+0]);
                ffma2(a1, q2[d+1], kj[d+1]);
                ffma2(a2, q2[d+2], kj[d+2]);
                ffma2(a3, q2[d+3], kj[d+3]);
            }
            float lo, hi, ss;
            upk2(lo, hi, a0); ss  = lo + hi;
            upk2(lo, hi, a1); ss += lo + hi;
            upk2(lo, hi, a2); ss += lo + hi;
            upk2(lo, hi, a3); ss += lo + hi;
            s[jj] = ss * 0.125f;
        }
        float cm = s[0];
#pragma unroll
        for (int jj = 1; jj < 16; ++jj) cm = fmaxf(cm, s[jj]);
        const float nm = fmaxf(m, cm);
        const float sc = __expf(m - nm);
        m = nm;
        l *= sc;
        const unsigned long long sc2 = pk2(sc, sc);
#pragma unroll
        for (int d = 0; d < 32; ++d) fmul2(o2[d], sc2);
#pragma unroll
        for (int jj = 0; jj < 16; ++jj) {
            const float p = __expf(s[jj] - nm);
            l += p;
            const unsigned long long p2 = pk2(p, p);
            const unsigned long long* vj = V2 + (c * 16 + jj) * 32;
#pragma unroll
            for (int d = 0; d < 32; ++d) ffma2(o2[d], p2, vj[d]);
        }
    }

    const float inv = 1.0f / l;
    float* Og = att + (size_t)(w * WIN + tid) * HDIM + hd_i * HD;
#pragma unroll
    for (int d = 0; d < 16; ++d) {
        float l0, h0, l1, h1;
        upk2(l0, h0, o2[2*d]);
        upk2(l1, h1, o2[2*d+1]);
        *(float4*)(Og + d * 4) = make_float4(
            rna_tf32(l0 * inv), rna_tf32(h0 * inv),
            rna_tf32(l1 * inv), rna_tf32(h1 * inv));
    }
}

// ---------------------------------------------------------------------------
extern "C" void kernel_launch(void* const* d_in, const int* in_sizes, int n_in,
                              void* d_out, int out_size)
{
    (void)in_sizes; (void)n_in; (void)out_size;
    const float* x     = (const float*)d_in[0];
    const float* w_in  = (const float*)d_in[1];
    const float* b_in  = (const float*)d_in[2];
    const float* w_out = (const float*)d_in[3];
    const float* b_out = (const float*)d_in[4];
    float* out = (float*)d_out;

    float *qkv, *xr, *wir, *wor, *att;
    cudaGetSymbolAddress((void**)&qkv, g_qkv);
    cudaGetSymbolAddress((void**)&xr,  g_xr);
    cudaGetSymbolAddress((void**)&wir, g_wir);
    cudaGetSymbolAddress((void**)&wor, g_wor);
    cudaGetSymbolAddress((void**)&att, g_att);

    cudaFuncSetAttribute(gemm_tf32,
                         cudaFuncAttributeMaxDynamicSharedMemorySize, GEMM_SMEM);
    cudaFuncSetAttribute(attn_kernel,
                         cudaFuncAttributeMaxDynamicSharedMemorySize, ATTN_SMEM);

    // round fp32 inputs to tf32 (rna)
    round_tf32<<<(M_TOK  * HDIM) / 1024, 256>>>((const float4*)x,     (float4*)xr);
    round_tf32<<<(QKVDIM * HDIM) / 1024, 256>>>((const float4*)w_in,  (float4*)wir);
    round_tf32<<<(HDIM   * HDIM) / 1024, 256>>>((const float4*)w_out, (float4*)wor);

    // Stage 1: QKV projection
    gemm_tf32<<<dim3(M_TOK / 128, QKVDIM / 128), 256, GEMM_SMEM>>>(
        xr, wir, b_in, qkv, QKVDIM);

    // Stage 2: windowed attention (online softmax, emits tf32-rounded fp32)
    attn_kernel<<<dim3(NWIN, NHEAD), 128, ATTN_SMEM>>>(qkv, att);

    // Stage 3: output projection
    gemm_tf32<<<dim3(M_TOK / 128, HDIM / 128), 256, GEMM_SMEM>>>(
        att, wor, b_out, out, HDIM);
}